// round 3
// baseline (speedup 1.0000x reference)
#include <cuda_runtime.h>

// GINConv fused: out = A @ (X @ W)  (reassociated from (A@X) @ W)
// N=100000 nodes, E edges (CSR), D_IN = D_OUT = 32.

#define MAX_N 100000
#define D 32

// Scratch for Y = X @ W  (12.8 MB, fits in L2) — static to obey no-alloc rule.
__device__ float g_Y[MAX_N * D];

// ---------------------------------------------------------------------------
// Kernel 1: Y = X @ W.  One warp per node row; lane j owns output feature j.
// ---------------------------------------------------------------------------
__global__ void __launch_bounds__(256) gin_transform(
    const float* __restrict__ X, const float* __restrict__ W, int n)
{
    __shared__ float Ws[D * D];   // 4 KB
    int tid = threadIdx.x;
    for (int i = tid; i < D * D; i += blockDim.x) Ws[i] = W[i];
    __syncthreads();

    int lane = tid & 31;
    int warp = (blockIdx.x * (blockDim.x >> 5)) + (tid >> 5);
    if (warp >= n) return;

    float x = X[warp * D + lane];          // coalesced 128B row load
    float acc = 0.0f;
    #pragma unroll
    for (int k = 0; k < D; k++) {
        float xv = __shfl_sync(0xffffffffu, x, k);
        acc = fmaf(xv, Ws[k * D + lane], acc);   // conflict-free: consecutive
    }
    g_Y[warp * D + lane] = acc;
}

// ---------------------------------------------------------------------------
// Kernel 2: out[r] = sum_{e in [rp[r], rp[r+1])} Y[ci[e]]
// One warp per row. Lanes load 32 column indices coalesced, shfl-broadcast
// each, then all 32 lanes do one coalesced 128B gather of that Y row.
// ---------------------------------------------------------------------------
__global__ void __launch_bounds__(256) gin_aggregate(
    const int* __restrict__ rp, const int* __restrict__ ci,
    float* __restrict__ out, int n)
{
    int tid  = threadIdx.x;
    int lane = tid & 31;
    int warp = (blockIdx.x * (blockDim.x >> 5)) + (tid >> 5);
    if (warp >= n) return;

    int start = rp[warp];
    int end   = rp[warp + 1];

    float acc = 0.0f;
    for (int e = start; e < end; e += 32) {
        int rem = end - e;
        int myc = 0;
        if (lane < rem) myc = __ldg(&ci[e + lane]);   // coalesced index load

        int cnt = rem < 32 ? rem : 32;
        // Full-batch fast path: fixed trip count lets ptxas unroll and batch
        // the gathers for MLP.
        if (cnt == 32) {
            #pragma unroll
            for (int k = 0; k < 32; k++) {
                int c = __shfl_sync(0xffffffffu, myc, k);
                acc += __ldg(&g_Y[c * D + lane]);     // coalesced 128B gather
            }
        } else {
            #pragma unroll 4
            for (int k = 0; k < cnt; k++) {
                int c = __shfl_sync(0xffffffffu, myc, k);
                acc += __ldg(&g_Y[c * D + lane]);
            }
        }
    }
    out[warp * D + lane] = acc;   // also zeroes degree-0 rows
}

// ---------------------------------------------------------------------------
extern "C" void kernel_launch(void* const* d_in, const int* in_sizes, int n_in,
                              void* d_out, int out_size)
{
    const float* X  = (const float*)d_in[0];
    const float* W  = (const float*)d_in[1];
    const int*   rp = (const int*)d_in[2];
    const int*   ci = (const int*)d_in[3];
    float*       out = (float*)d_out;

    int n = in_sizes[0] / D;          // number of nodes

    const int THREADS = 256;
    const int WARPS_PER_BLOCK = THREADS / 32;
    int blocks = (n + WARPS_PER_BLOCK - 1) / WARPS_PER_BLOCK;

    gin_transform<<<blocks, THREADS>>>(X, W, n);
    gin_aggregate<<<blocks, THREADS>>>(rp, ci, out, n);
}

// round 4
// speedup vs baseline: 1.3274x; 1.3274x over previous
#include <cuda_runtime.h>

// GINConv fused: out = A @ (X @ W)  (reassociated from (A@X) @ W)
// N=100000 nodes, E edges (CSR), D_IN = D_OUT = 32.

#define MAX_N 100000
#define D 32

// Scratch for Y = X @ W  (12.8 MB, fits in L2) — static to obey no-alloc rule.
__device__ __align__(16) float g_Y[MAX_N * D];

// packed f32x2 accumulate: a += b (two fp32 adds in one instruction)
__device__ __forceinline__ void add2(unsigned long long& a, unsigned long long b) {
    asm("add.rn.f32x2 %0, %0, %1;" : "+l"(a) : "l"(b));
}

// ---------------------------------------------------------------------------
// Kernel 1: Y = X @ W.  One warp per 4 rows. Lane (g,s): g = edge-row group
// (0..3), s = feature quarter (0..7). Thread computes float4 of outputs for
// row base+g, cols s*4..s*4+3. X broadcast via padded smem, W via LDS.128.
// ---------------------------------------------------------------------------
__global__ void __launch_bounds__(256) gin_transform(
    const float* __restrict__ X, const float* __restrict__ W, int n)
{
    __shared__ __align__(16) float Ws[D * D];        // 4 KB
    __shared__ __align__(16) float Xs[8][4 * 36];    // 4 rows/warp, pad stride 36

    int tid = threadIdx.x;
    for (int i = tid; i < D * D; i += blockDim.x) Ws[i] = W[i];
    __syncthreads();

    int lane = tid & 31;
    int wip  = tid >> 5;
    int warp = blockIdx.x * 8 + wip;
    int row4 = warp * 4;
    if (row4 >= n) return;

    int g = lane >> 3, s = lane & 7;
    int r = row4 + g;

    float4 xv = make_float4(0.f, 0.f, 0.f, 0.f);
    if (r < n) xv = ((const float4*)X)[r * 8 + s];       // coalesced 512B/warp
    float* xrow = &Xs[wip][g * 36];
    *((float4*)(xrow + s * 4)) = xv;                     // 16B-aligned stage
    __syncwarp();

    float4 acc = make_float4(0.f, 0.f, 0.f, 0.f);
    #pragma unroll
    for (int k = 0; k < D; k++) {
        float  xk = xrow[k];                             // 4-addr broadcast, no conflict
        float4 wr = ((const float4*)Ws)[k * 8 + s];      // LDS.128 broadcast
        acc.x = fmaf(xk, wr.x, acc.x);
        acc.y = fmaf(xk, wr.y, acc.y);
        acc.z = fmaf(xk, wr.z, acc.z);
        acc.w = fmaf(xk, wr.w, acc.w);
    }
    if (r < n) ((float4*)g_Y)[r * 8 + s] = acc;          // coalesced 512B/warp
}

// ---------------------------------------------------------------------------
// Kernel 2: out[r] = sum_{e in [rp[r], rp[r+1])} Y[ci[e]]
// One warp per row, 4 edges per step: group g (8 lanes) gathers the whole
// 128B row of edge e+k+g as 16B per lane (one LDG.128 covers 4 edges).
// Packed f32x2 accumulation; cross-group reduce at the end.
// ---------------------------------------------------------------------------
__global__ void __launch_bounds__(256) gin_aggregate(
    const int* __restrict__ rp, const int* __restrict__ ci,
    float* __restrict__ out, int n)
{
    int tid  = threadIdx.x;
    int lane = tid & 31;
    int warp = blockIdx.x * 8 + (tid >> 5);
    if (warp >= n) return;

    int start = rp[warp];
    int end   = rp[warp + 1];
    int grp = lane >> 3, sub = lane & 7;
    const ulonglong2* __restrict__ Y2 = (const ulonglong2*)g_Y;  // row = 8 x 16B

    unsigned long long a01 = 0ull, a23 = 0ull;   // bitwise {0.f,0.f} pairs

    for (int e = start; e < end; e += 32) {
        int rem = end - e;
        int myc = -1;
        if (lane < rem) myc = __ldg(&ci[e + lane]);    // coalesced index load

        if (rem >= 32) {
            #pragma unroll
            for (int k = 0; k < 32; k += 4) {
                int c = __shfl_sync(0xffffffffu, myc, k + grp);
                ulonglong2 v = __ldg(&Y2[c * 8 + sub]); // LDG.128: 4 rows/warp
                add2(a01, v.x);
                add2(a23, v.y);
            }
        } else {
            #pragma unroll 4
            for (int k = 0; k < rem; k += 4) {
                int c = __shfl_sync(0xffffffffu, myc, k + grp);
                if (c >= 0) {
                    ulonglong2 v = __ldg(&Y2[c * 8 + sub]);
                    add2(a01, v.x);
                    add2(a23, v.y);
                }
            }
        }
    }

    // fold the 4 edge-groups: lanes {s, s+8, s+16, s+24} hold same features
    add2(a01, __shfl_xor_sync(0xffffffffu, a01, 8));
    add2(a23, __shfl_xor_sync(0xffffffffu, a23, 8));
    add2(a01, __shfl_xor_sync(0xffffffffu, a01, 16));
    add2(a23, __shfl_xor_sync(0xffffffffu, a23, 16));

    if (lane < 8) {
        ulonglong2 r;
        r.x = a01; r.y = a23;
        ((ulonglong2*)out)[warp * 8 + lane] = r;       // coalesced 128B row
    }
}

// ---------------------------------------------------------------------------
extern "C" void kernel_launch(void* const* d_in, const int* in_sizes, int n_in,
                              void* d_out, int out_size)
{
    const float* X  = (const float*)d_in[0];
    const float* W  = (const float*)d_in[1];
    const int*   rp = (const int*)d_in[2];
    const int*   ci = (const int*)d_in[3];
    float*       out = (float*)d_out;

    int n = in_sizes[0] / D;   // number of nodes

    const int THREADS = 256;
    int tblocks = (n + (8 * 4) - 1) / (8 * 4);   // 4 rows per warp
    int ablocks = (n + 8 - 1) / 8;               // 1 row per warp

    gin_transform<<<tblocks, THREADS>>>(X, W, n);
    gin_aggregate<<<ablocks, THREADS>>>(rp, ci, out, n);
}